// round 16
// baseline (speedup 1.0000x reference)
#include <cuda_runtime.h>
#include <cuda_fp16.h>
#include <cstdint>

typedef unsigned short ushort_t;

#define N_NODES   100000
#define N_EDGES   800000
#define HIDF      128
#define EMBF      64
#define OUTF      8
#define N_GRAPHS  64
#define ELLPAD    64

// ---------------- scratch (device globals; no allocation) ----------------
__device__ int   g_batch[N_NODES];
__device__ int   g_deg[N_NODES];
__device__ int   g_ell[(size_t)N_NODES * ELLPAD];
// fp16 activation planes
__device__ ushort_t g_xh [(size_t)N_NODES * HIDF];
__device__ ushort_t g_h1h[(size_t)N_NODES * HIDF];
__device__ ushort_t g_h2h[(size_t)N_NODES * HIDF];
__device__ ushort_t g_ag [(size_t)N_NODES * HIDF];
// weights fp16, layout [128 out][256 k] row-major
__device__ ushort_t g_wh1[128 * 256];
__device__ ushort_t g_wh2[128 * 256];
__device__ float g_pool[N_GRAPHS * HIDF];
__device__ int   g_cnt[N_GRAPHS];

// ---------------- helpers ----------------
__device__ __forceinline__ uint32_t smem_u32(const void* p) {
    uint32_t a;
    asm("{ .reg .u64 t; cvta.to.shared.u64 t, %1; cvt.u32.u64 %0, t; }" : "=r"(a) : "l"(p));
    return a;
}
__device__ __forceinline__ ushort_t f16_of(float v) {
    ushort_t h;
    asm("cvt.rn.f16.f32 %0, %1;" : "=h"(h) : "f"(v));
    return h;
}
__device__ __forceinline__ float f16_to_f32(ushort_t h) {
    float f;
    asm("cvt.f32.f16 %0, %1;" : "=f"(f) : "h"(h));
    return f;
}
// int64-vs-int32 detection from 8 fixed odd 32-bit words of edge_index.
__device__ __forceinline__ int ei_is64(const unsigned* w) {
    unsigned o = w[1] | w[3] | w[5] | w[7] | w[9] | w[11] | w[13] | w[15];
    return o == 0u;
}
__device__ __forceinline__ void cp16(uint32_t dst, const void* src) {
    asm volatile("cp.async.cg.shared.global [%0], [%1], 16;" :: "r"(dst), "l"(src));
}
__device__ __forceinline__ void cp16z(uint32_t dst, const void* src, bool ok) {
    int sz = ok ? 16 : 0;
    asm volatile("cp.async.cg.shared.global [%0], [%1], 16, %2;"
                 :: "r"(dst), "l"(src), "r"(sz));
}
#define CP_COMMIT() asm volatile("cp.async.commit_group;" ::: "memory")
#define CP_WAIT(n)  asm volatile("cp.async.wait_group %0;" :: "n"(n) : "memory")

__device__ __forceinline__ void ldsm_x4(unsigned* r, uint32_t a) {
    asm volatile("ldmatrix.sync.aligned.m8n8.x4.shared.b16 {%0,%1,%2,%3}, [%4];"
                 : "=r"(r[0]), "=r"(r[1]), "=r"(r[2]), "=r"(r[3]) : "r"(a));
}
__device__ __forceinline__ void ldsm_x2(unsigned* r, uint32_t a) {
    asm volatile("ldmatrix.sync.aligned.m8n8.x2.shared.b16 {%0,%1}, [%2];"
                 : "=r"(r[0]), "=r"(r[1]) : "r"(a));
}
__device__ __forceinline__ void mma_f16(float* c, const unsigned* a, const unsigned* b) {
    asm volatile(
        "mma.sync.aligned.m16n8k16.row.col.f32.f16.f16.f32 "
        "{%0,%1,%2,%3}, {%4,%5,%6,%7}, {%8,%9}, {%0,%1,%2,%3};"
        : "+f"(c[0]), "+f"(c[1]), "+f"(c[2]), "+f"(c[3])
        : "r"(a[0]), "r"(a[1]), "r"(a[2]), "r"(a[3]), "r"(b[0]), "r"(b[1]));
}

// ---------------- fused prep: x fp16 + weight fp16 + batch + zeroing ----------------
__global__ void k_prep_init(const float* __restrict__ x, const void* __restrict__ ei,
                            const void* __restrict__ batch,
                            const float* __restrict__ W1l, const float* __restrict__ W1r,
                            const float* __restrict__ W2l, const float* __restrict__ W2r) {
    int idx = blockIdx.x * blockDim.x + threadIdx.x;
    const int n4 = N_NODES * HIDF / 4;
    if (idx < n4) {  // x -> fp16 plane
        float4 v = ((const float4*)x)[idx];
        ushort4 hv;
        hv.x = f16_of(v.x); hv.y = f16_of(v.y);
        hv.z = f16_of(v.z); hv.w = f16_of(v.w);
        ((ushort4*)g_xh)[idx] = hv;
    }
    if (idx < 128 * 256) {  // weight concat, fp16 round
        int j = idx >> 8, k = idx & 255;
        float w1 = (k < 128) ? W1l[j * 128 + k] : W1r[j * 128 + (k - 128)];
        float w2 = (k < 128) ? W2l[j * 128 + k] : W2r[j * 128 + (k - 128)];
        g_wh1[idx] = f16_of(w1);
        g_wh2[idx] = f16_of(w2);
    }
    if (idx < N_NODES) {  // batch convert + zero deg
        int is64 = ei_is64((const unsigned*)ei);
        if (is64) g_batch[idx] = (int)((const long long*)batch)[idx];
        else      g_batch[idx] = ((const int*)batch)[idx];
        g_deg[idx] = 0;
    }
    if (idx < N_GRAPHS * HIDF) g_pool[idx] = 0.f;
    if (idx < N_GRAPHS)        g_cnt[idx]  = 0;
}

// ---------------- ELL build: convert edges inline + atomic cursor ----------------
__global__ void k_fill_ell(const void* __restrict__ ei) {
    int i = blockIdx.x * blockDim.x + threadIdx.x;
    if (i >= N_EDGES) return;
    int is64 = ei_is64((const unsigned*)ei);
    int s, d;
    if (is64) {
        const long long* p = (const long long*)ei;
        s = (int)p[i];
        d = (int)p[N_EDGES + i];
    } else {
        const int* p = (const int*)ei;
        s = p[i];
        d = p[N_EDGES + i];
    }
    int slot = atomicAdd(&g_deg[d], 1);
    if (slot < ELLPAD) g_ell[(size_t)d * ELLPAD + slot] = s;
}

// ---------------- mean aggregation (ELL): fp16 gather, fp32 accumulate ----------------
__global__ void k_agg(const ushort_t* __restrict__ Hp, ushort_t* __restrict__ P) {
    int node = (blockIdx.x * blockDim.x + threadIdx.x) >> 5;
    int lane = threadIdx.x & 31;
    if (node >= N_NODES) return;
    const int* ell = g_ell + (size_t)node * ELLPAD;
    int d = g_deg[node];
    int dcap = min(d, ELLPAD);
    float4 acc = make_float4(0.f, 0.f, 0.f, 0.f);
    int e = 0;
    for (; e + 4 <= dcap; e += 4) {
        int s0 = ell[e], s1 = ell[e + 1], s2 = ell[e + 2], s3 = ell[e + 3];
        uint2 v0 = ((const uint2*)(Hp + (size_t)s0 * HIDF))[lane];
        uint2 v1 = ((const uint2*)(Hp + (size_t)s1 * HIDF))[lane];
        uint2 v2 = ((const uint2*)(Hp + (size_t)s2 * HIDF))[lane];
        uint2 v3 = ((const uint2*)(Hp + (size_t)s3 * HIDF))[lane];
#pragma unroll
        for (int j = 0; j < 4; j++) {
            uint2 v = (j == 0) ? v0 : (j == 1) ? v1 : (j == 2) ? v2 : v3;
            float2 a = __half22float2(*(__half2*)&v.x);
            float2 b = __half22float2(*(__half2*)&v.y);
            acc.x += a.x; acc.y += a.y; acc.z += b.x; acc.w += b.y;
        }
    }
    for (; e < dcap; e++) {
        uint2 v = ((const uint2*)(Hp + (size_t)ell[e] * HIDF))[lane];
        float2 a = __half22float2(*(__half2*)&v.x);
        float2 b = __half22float2(*(__half2*)&v.y);
        acc.x += a.x; acc.y += a.y; acc.z += b.x; acc.w += b.y;
    }
    float inv = 1.0f / (float)max(d, 1);
    ushort4 hv;
    hv.x = f16_of(acc.x * inv); hv.y = f16_of(acc.y * inv);
    hv.z = f16_of(acc.z * inv); hv.w = f16_of(acc.w * inv);
    *(ushort4*)(P + (size_t)node * HIDF + lane * 4) = hv;
}

// ---------------- cp.async 3-stage pure-fp16 HMMA GEMM ----------------
// C = f16(A) * f16(W), fp32 accumulate; fp16 plane output.
// Tiles per stage: A, B (2 x 8KB); 3 stages = 48KB smem; 3 CTAs/SM target.
#define TILEB 8192
#define NSTG  3
#define TPS   2
#define GSMEM (NSTG * TPS * TILEB)

__device__ __forceinline__ uint32_t swz(int r, int c) {
    return (uint32_t)((r << 6) + ((c ^ ((r >> 1) & 3)) << 4));
}

__device__ __forceinline__ void stage_issue(
    int kb, int s, int row0, int r, int colseg, bool okA, uint32_t sb,
    const ushort_t* Ap, const ushort_t* Hp, const ushort_t* Wh)
{
    const ushort_t* S = (kb < 4) ? Ap : Hp;
    int kc = (kb & 3) * 32;
    int k0 = kb * 32;
    int c0 = colseg >> 3;
    uint32_t base = sb + (uint32_t)s * TPS * TILEB;
    uint32_t d0 = swz(r, c0), d1 = swz(r, c0 + 1);
    const ushort_t* ga = S + (size_t)(row0 + r) * HIDF + kc + colseg;
    cp16z(base + d0, ga,     okA);
    cp16z(base + d1, ga + 8, okA);
    const ushort_t* gb = Wh + (size_t)r * 256 + k0 + colseg;
    cp16(base + TILEB + d0, gb);
    cp16(base + TILEB + d1, gb + 8);
    CP_COMMIT();
}

__global__ void __launch_bounds__(256, 3)
k_gemm_pipe(const ushort_t* __restrict__ Ap, const ushort_t* __restrict__ Hp,
            const ushort_t* __restrict__ Wh,
            const float* __restrict__ bias, ushort_t* __restrict__ Hoh) {
    extern __shared__ ushort_t sdyn[];
    __shared__ float bsm[128];
    uint32_t sb = smem_u32(sdyn);
    int tid = threadIdx.x;
    int warp = tid >> 5, lane = tid & 31;
    int wm = warp & 1, wn = warp >> 1;        // 2 x 4 warp grid
    int gq = lane >> 2, tig = lane & 3;       // quad-pair layout
    int row0 = blockIdx.x * 128;
    if (tid < 128) bsm[tid] = bias[tid];

    int r = tid >> 1;
    int colseg = (tid & 1) * 16;
    bool okA = (row0 + r) < N_NODES;
    int arow = (lane & 7) + 8 * ((lane >> 3) & 1);
    int achk = lane >> 4;
    int brow = lane & 7;
    int bchk = (lane >> 3) & 1;

    float acc[4][4][4];
#pragma unroll
    for (int mi = 0; mi < 4; mi++)
#pragma unroll
        for (int ni = 0; ni < 4; ni++)
#pragma unroll
            for (int q = 0; q < 4; q++) acc[mi][ni][q] = 0.f;

    stage_issue(0, 0, row0, r, colseg, okA, sb, Ap, Hp, Wh);
    stage_issue(1, 1, row0, r, colseg, okA, sb, Ap, Hp, Wh);

    for (int kb = 0; kb < 8; kb++) {
        int s = kb % NSTG;
        if (kb + 1 < 8) CP_WAIT(1); else CP_WAIT(0);
        __syncthreads();
        if (kb + 2 < 8)
            stage_issue(kb + 2, (kb + 2) % NSTG, row0, r, colseg, okA, sb, Ap, Hp, Wh);
        uint32_t base = sb + (uint32_t)s * TPS * TILEB;
        uint32_t a_s = base;
        uint32_t b_s = base + TILEB;
#pragma unroll
        for (int ks = 0; ks < 2; ks++) {
            int ca = ks * 2 + achk;
            int cb = ks * 2 + bchk;
            unsigned af[4][4], bf[4][2];
#pragma unroll
            for (int mi = 0; mi < 4; mi++) {
                int m = wm * 64 + mi * 16 + arow;
                ldsm_x4(af[mi], a_s + swz(m, ca));
            }
#pragma unroll
            for (int ni = 0; ni < 4; ni++) {
                int n = wn * 32 + ni * 8 + brow;
                ldsm_x2(bf[ni], b_s + swz(n, cb));
            }
#pragma unroll
            for (int mi = 0; mi < 4; mi++)
#pragma unroll
                for (int ni = 0; ni < 4; ni++)
                    mma_f16(acc[mi][ni], af[mi], bf[ni]);
        }
    }
    __syncthreads();
    // ---- epilogue: fp16 plane output ----
#pragma unroll
    for (int mi = 0; mi < 4; mi++) {
#pragma unroll
        for (int ni = 0; ni < 4; ni++) {
            int colc = wn * 32 + ni * 8 + tig * 2;
            int ra = row0 + wm * 64 + mi * 16 + gq;
            int rb = ra + 8;
            if (ra < N_NODES) {
                ushort2 hv;
                hv.x = f16_of(fmaxf(acc[mi][ni][0] + bsm[colc], 0.f));
                hv.y = f16_of(fmaxf(acc[mi][ni][1] + bsm[colc + 1], 0.f));
                *(ushort2*)(Hoh + (size_t)ra * HIDF + colc) = hv;
            }
            if (rb < N_NODES) {
                ushort2 hv;
                hv.x = f16_of(fmaxf(acc[mi][ni][2] + bsm[colc], 0.f));
                hv.y = f16_of(fmaxf(acc[mi][ni][3] + bsm[colc + 1], 0.f));
                *(ushort2*)(Hoh + (size_t)rb * HIDF + colc) = hv;
            }
        }
    }
}

// ---------------- sorted segment-mean pooling (fp16 input, 128 nodes/block) ----------------
__global__ void k_pool(const ushort_t* __restrict__ H) {
    int t = threadIdx.x;
    int base = blockIdx.x * 128;
    if (base >= N_NODES) return;
    int end = min(base + 128, N_NODES);
    int cur = g_batch[base];
    float acc = 0.f;
    int run = 0;
    for (int n = base; n < end; n++) {
        int g = g_batch[n];
        if (g != cur) {
            atomicAdd(&g_pool[cur * HIDF + t], acc);
            if (t == 0) atomicAdd(&g_cnt[cur], run);
            acc = 0.f; run = 0; cur = g;
        }
        acc += f16_to_f32(H[(size_t)n * HIDF + t]);
        run++;
    }
    atomicAdd(&g_pool[cur * HIDF + t], acc);
    if (t == 0) atomicAdd(&g_cnt[cur], run);
}

// ---------------- head: one block per graph, one warp per output ----------------
__global__ void k_head(const float* __restrict__ embed, const float* __restrict__ Wlin,
                       const float* __restrict__ blin, float* __restrict__ out) {
    int g = blockIdx.x;
    int o = threadIdx.x >> 5;
    int lane = threadIdx.x & 31;
    float c = (float)max(g_cnt[g], 1);
    float inv = 1.0f / c;
    const float* wr = Wlin + o * (HIDF + EMBF);
    float s = 0.f;
    for (int k = lane; k < HIDF; k += 32) s += g_pool[g * HIDF + k] * inv * wr[k];
    for (int k = lane; k < EMBF; k += 32) s += embed[g * EMBF + k] * wr[HIDF + k];
#pragma unroll
    for (int off = 16; off > 0; off >>= 1)
        s += __shfl_down_sync(0xFFFFFFFF, s, off);
    if (lane == 0) out[g * OUTF + o] = s + blin[o];
}

// ---------------- launch ----------------
extern "C" void kernel_launch(void* const* d_in, const int* in_sizes, int n_in,
                              void* d_out, int out_size) {
    const float* x     = (const float*)d_in[0];
    const void*  ei    = d_in[1];
    const void*  batch = d_in[2];
    const float* embed = (const float*)d_in[3];
    const float* W1l   = (const float*)d_in[4];
    const float* b1l   = (const float*)d_in[5];
    const float* W1r   = (const float*)d_in[6];
    const float* W2l   = (const float*)d_in[7];
    const float* b2l   = (const float*)d_in[8];
    const float* W2r   = (const float*)d_in[9];
    const float* Wlin  = (const float*)d_in[10];
    const float* blin  = (const float*)d_in[11];
    float* out = (float*)d_out;

    ushort_t *xh_p, *h1h_p, *h2h_p, *ag_p, *wh1_p, *wh2_p;
    cudaGetSymbolAddress((void**)&xh_p,  g_xh);
    cudaGetSymbolAddress((void**)&h1h_p, g_h1h);
    cudaGetSymbolAddress((void**)&h2h_p, g_h2h);
    cudaGetSymbolAddress((void**)&ag_p,  g_ag);
    cudaGetSymbolAddress((void**)&wh1_p, g_wh1);
    cudaGetSymbolAddress((void**)&wh2_p, g_wh2);

    cudaFuncSetAttribute(k_gemm_pipe, cudaFuncAttributeMaxDynamicSharedMemorySize, GSMEM);

    const int TB = 256;
    const int n4 = N_NODES * HIDF / 4;
    k_prep_init<<<(n4 + TB - 1) / TB, TB>>>(x, ei, batch, W1l, W1r, W2l, W2r);   // 1
    k_fill_ell<<<(N_EDGES + TB - 1) / TB, TB>>>(ei);                              // 2

    const int NB = (N_NODES + 127) / 128;
    // layer 1
    k_agg<<<(N_NODES + 7) / 8, 256>>>(xh_p, ag_p);                                // 3
    k_gemm_pipe<<<NB, 256, GSMEM>>>(ag_p, xh_p, wh1_p, b1l, h1h_p);               // 4 <- profiled
    // layer 2
    k_agg<<<(N_NODES + 7) / 8, 256>>>(h1h_p, ag_p);                               // 5
    k_gemm_pipe<<<NB, 256, GSMEM>>>(ag_p, h1h_p, wh2_p, b2l, h2h_p);              // 6
    // pooling + head
    k_pool<<<(N_NODES + 127) / 128, 128>>>(h2h_p);                                 // 7
    k_head<<<N_GRAPHS, 256>>>(embed, Wlin, blin, out);                             // 8
}

// round 17
// speedup vs baseline: 1.2557x; 1.2557x over previous
#include <cuda_runtime.h>
#include <cuda_fp16.h>
#include <cstdint>

typedef unsigned short ushort_t;

#define N_NODES   100000
#define N_EDGES   800000
#define HIDF      128
#define EMBF      64
#define OUTF      8
#define N_GRAPHS  64
#define ELLPAD    64

// ---------------- scratch (device globals; no allocation) ----------------
__device__ int   g_batch[N_NODES];
__device__ int   g_deg[N_NODES];
__device__ int   g_ell[(size_t)N_NODES * ELLPAD];
// fp16 activation planes
__device__ ushort_t g_xh [(size_t)N_NODES * HIDF];
__device__ ushort_t g_h1h[(size_t)N_NODES * HIDF];
__device__ ushort_t g_h2h[(size_t)N_NODES * HIDF];
__device__ ushort_t g_ag [(size_t)N_NODES * HIDF];
// weights fp16, layout [128 out][256 k] row-major
__device__ ushort_t g_wh1[128 * 256];
__device__ ushort_t g_wh2[128 * 256];
__device__ float g_pool[N_GRAPHS * HIDF];
__device__ int   g_cnt[N_GRAPHS];

// ---------------- helpers ----------------
__device__ __forceinline__ uint32_t smem_u32(const void* p) {
    uint32_t a;
    asm("{ .reg .u64 t; cvta.to.shared.u64 t, %1; cvt.u32.u64 %0, t; }" : "=r"(a) : "l"(p));
    return a;
}
__device__ __forceinline__ ushort_t f16_of(float v) {
    ushort_t h;
    asm("cvt.rn.f16.f32 %0, %1;" : "=h"(h) : "f"(v));
    return h;
}
__device__ __forceinline__ float f16_to_f32(ushort_t h) {
    float f;
    asm("cvt.f32.f16 %0, %1;" : "=f"(f) : "h"(h));
    return f;
}
// int64-vs-int32 detection from 8 fixed odd 32-bit words of edge_index.
__device__ __forceinline__ int ei_is64(const unsigned* w) {
    unsigned o = w[1] | w[3] | w[5] | w[7] | w[9] | w[11] | w[13] | w[15];
    return o == 0u;
}
__device__ __forceinline__ void cp16(uint32_t dst, const void* src) {
    asm volatile("cp.async.cg.shared.global [%0], [%1], 16;" :: "r"(dst), "l"(src));
}
__device__ __forceinline__ void cp16z(uint32_t dst, const void* src, bool ok) {
    int sz = ok ? 16 : 0;
    asm volatile("cp.async.cg.shared.global [%0], [%1], 16, %2;"
                 :: "r"(dst), "l"(src), "r"(sz));
}
#define CP_COMMIT() asm volatile("cp.async.commit_group;" ::: "memory")
#define CP_WAIT(n)  asm volatile("cp.async.wait_group %0;" :: "n"(n) : "memory")

__device__ __forceinline__ void ldsm_x4(unsigned* r, uint32_t a) {
    asm volatile("ldmatrix.sync.aligned.m8n8.x4.shared.b16 {%0,%1,%2,%3}, [%4];"
                 : "=r"(r[0]), "=r"(r[1]), "=r"(r[2]), "=r"(r[3]) : "r"(a));
}
__device__ __forceinline__ void ldsm_x2(unsigned* r, uint32_t a) {
    asm volatile("ldmatrix.sync.aligned.m8n8.x2.shared.b16 {%0,%1}, [%2];"
                 : "=r"(r[0]), "=r"(r[1]) : "r"(a));
}
__device__ __forceinline__ void mma_f16(float* c, const unsigned* a, const unsigned* b) {
    asm volatile(
        "mma.sync.aligned.m16n8k16.row.col.f32.f16.f16.f32 "
        "{%0,%1,%2,%3}, {%4,%5,%6,%7}, {%8,%9}, {%0,%1,%2,%3};"
        : "+f"(c[0]), "+f"(c[1]), "+f"(c[2]), "+f"(c[3])
        : "r"(a[0]), "r"(a[1]), "r"(a[2]), "r"(a[3]), "r"(b[0]), "r"(b[1]));
}

// ---------------- fused prep: x fp16 + weight fp16 + batch + zeroing ----------------
__global__ void k_prep_init(const float* __restrict__ x, const void* __restrict__ ei,
                            const void* __restrict__ batch,
                            const float* __restrict__ W1l, const float* __restrict__ W1r,
                            const float* __restrict__ W2l, const float* __restrict__ W2r) {
    int idx = blockIdx.x * blockDim.x + threadIdx.x;
    const int n4 = N_NODES * HIDF / 4;
    if (idx < n4) {  // x -> fp16 plane
        float4 v = ((const float4*)x)[idx];
        ushort4 hv;
        hv.x = f16_of(v.x); hv.y = f16_of(v.y);
        hv.z = f16_of(v.z); hv.w = f16_of(v.w);
        ((ushort4*)g_xh)[idx] = hv;
    }
    if (idx < 128 * 256) {  // weight concat, fp16 round
        int j = idx >> 8, k = idx & 255;
        float w1 = (k < 128) ? W1l[j * 128 + k] : W1r[j * 128 + (k - 128)];
        float w2 = (k < 128) ? W2l[j * 128 + k] : W2r[j * 128 + (k - 128)];
        g_wh1[idx] = f16_of(w1);
        g_wh2[idx] = f16_of(w2);
    }
    if (idx < N_NODES) {  // batch convert + zero deg
        int is64 = ei_is64((const unsigned*)ei);
        if (is64) g_batch[idx] = (int)((const long long*)batch)[idx];
        else      g_batch[idx] = ((const int*)batch)[idx];
        g_deg[idx] = 0;
    }
    if (idx < N_GRAPHS * HIDF) g_pool[idx] = 0.f;
    if (idx < N_GRAPHS)        g_cnt[idx]  = 0;
}

// ---------------- ELL build: convert edges inline + atomic cursor ----------------
__global__ void k_fill_ell(const void* __restrict__ ei) {
    int i = blockIdx.x * blockDim.x + threadIdx.x;
    if (i >= N_EDGES) return;
    int is64 = ei_is64((const unsigned*)ei);
    int s, d;
    if (is64) {
        const long long* p = (const long long*)ei;
        s = (int)p[i];
        d = (int)p[N_EDGES + i];
    } else {
        const int* p = (const int*)ei;
        s = p[i];
        d = p[N_EDGES + i];
    }
    int slot = atomicAdd(&g_deg[d], 1);
    if (slot < ELLPAD) g_ell[(size_t)d * ELLPAD + slot] = s;
}

// ---------------- mean aggregation (ELL): fp16 gather, fp32 accumulate ----------------
__global__ void k_agg(const ushort_t* __restrict__ Hp, ushort_t* __restrict__ P) {
    int node = (blockIdx.x * blockDim.x + threadIdx.x) >> 5;
    int lane = threadIdx.x & 31;
    if (node >= N_NODES) return;
    const int* ell = g_ell + (size_t)node * ELLPAD;
    int d = g_deg[node];
    int dcap = min(d, ELLPAD);
    float4 acc = make_float4(0.f, 0.f, 0.f, 0.f);
    int e = 0;
    for (; e + 4 <= dcap; e += 4) {
        int s0 = ell[e], s1 = ell[e + 1], s2 = ell[e + 2], s3 = ell[e + 3];
        uint2 v0 = ((const uint2*)(Hp + (size_t)s0 * HIDF))[lane];
        uint2 v1 = ((const uint2*)(Hp + (size_t)s1 * HIDF))[lane];
        uint2 v2 = ((const uint2*)(Hp + (size_t)s2 * HIDF))[lane];
        uint2 v3 = ((const uint2*)(Hp + (size_t)s3 * HIDF))[lane];
#pragma unroll
        for (int j = 0; j < 4; j++) {
            uint2 v = (j == 0) ? v0 : (j == 1) ? v1 : (j == 2) ? v2 : v3;
            float2 a = __half22float2(*(__half2*)&v.x);
            float2 b = __half22float2(*(__half2*)&v.y);
            acc.x += a.x; acc.y += a.y; acc.z += b.x; acc.w += b.y;
        }
    }
    for (; e < dcap; e++) {
        uint2 v = ((const uint2*)(Hp + (size_t)ell[e] * HIDF))[lane];
        float2 a = __half22float2(*(__half2*)&v.x);
        float2 b = __half22float2(*(__half2*)&v.y);
        acc.x += a.x; acc.y += a.y; acc.z += b.x; acc.w += b.y;
    }
    float inv = 1.0f / (float)max(d, 1);
    ushort4 hv;
    hv.x = f16_of(acc.x * inv); hv.y = f16_of(acc.y * inv);
    hv.z = f16_of(acc.z * inv); hv.w = f16_of(acc.w * inv);
    *(ushort4*)(P + (size_t)node * HIDF + lane * 4) = hv;
}

// ---------------- cp.async 3-stage pure-fp16 HMMA GEMM ----------------
// C = f16(A) * f16(W), fp32 accumulate; fp16 plane output.
// Tiles per stage: A, B (2 x 8KB); 3 stages = 48KB smem.
// NO min-blocks bound: kernel needs ~128 regs (R16 spill regression).
#define TILEB 8192
#define NSTG  3
#define TPS   2
#define GSMEM (NSTG * TPS * TILEB)

__device__ __forceinline__ uint32_t swz(int r, int c) {
    return (uint32_t)((r << 6) + ((c ^ ((r >> 1) & 3)) << 4));
}

__device__ __forceinline__ void stage_issue(
    int kb, int s, int row0, int r, int colseg, bool okA, uint32_t sb,
    const ushort_t* Ap, const ushort_t* Hp, const ushort_t* Wh)
{
    const ushort_t* S = (kb < 4) ? Ap : Hp;
    int kc = (kb & 3) * 32;
    int k0 = kb * 32;
    int c0 = colseg >> 3;
    uint32_t base = sb + (uint32_t)s * TPS * TILEB;
    uint32_t d0 = swz(r, c0), d1 = swz(r, c0 + 1);
    const ushort_t* ga = S + (size_t)(row0 + r) * HIDF + kc + colseg;
    cp16z(base + d0, ga,     okA);
    cp16z(base + d1, ga + 8, okA);
    const ushort_t* gb = Wh + (size_t)r * 256 + k0 + colseg;
    cp16(base + TILEB + d0, gb);
    cp16(base + TILEB + d1, gb + 8);
    CP_COMMIT();
}

__global__ void __launch_bounds__(256)
k_gemm_pipe(const ushort_t* __restrict__ Ap, const ushort_t* __restrict__ Hp,
            const ushort_t* __restrict__ Wh,
            const float* __restrict__ bias, ushort_t* __restrict__ Hoh) {
    extern __shared__ ushort_t sdyn[];
    __shared__ float bsm[128];
    uint32_t sb = smem_u32(sdyn);
    int tid = threadIdx.x;
    int warp = tid >> 5, lane = tid & 31;
    int wm = warp & 1, wn = warp >> 1;        // 2 x 4 warp grid
    int gq = lane >> 2, tig = lane & 3;       // quad-pair layout
    int row0 = blockIdx.x * 128;
    if (tid < 128) bsm[tid] = bias[tid];

    int r = tid >> 1;
    int colseg = (tid & 1) * 16;
    bool okA = (row0 + r) < N_NODES;
    int arow = (lane & 7) + 8 * ((lane >> 3) & 1);
    int achk = lane >> 4;
    int brow = lane & 7;
    int bchk = (lane >> 3) & 1;

    float acc[4][4][4];
#pragma unroll
    for (int mi = 0; mi < 4; mi++)
#pragma unroll
        for (int ni = 0; ni < 4; ni++)
#pragma unroll
            for (int q = 0; q < 4; q++) acc[mi][ni][q] = 0.f;

    stage_issue(0, 0, row0, r, colseg, okA, sb, Ap, Hp, Wh);
    stage_issue(1, 1, row0, r, colseg, okA, sb, Ap, Hp, Wh);

    for (int kb = 0; kb < 8; kb++) {
        int s = kb % NSTG;
        if (kb + 1 < 8) CP_WAIT(1); else CP_WAIT(0);
        __syncthreads();
        if (kb + 2 < 8)
            stage_issue(kb + 2, (kb + 2) % NSTG, row0, r, colseg, okA, sb, Ap, Hp, Wh);
        uint32_t base = sb + (uint32_t)s * TPS * TILEB;
        uint32_t a_s = base;
        uint32_t b_s = base + TILEB;
#pragma unroll
        for (int ks = 0; ks < 2; ks++) {
            int ca = ks * 2 + achk;
            int cb = ks * 2 + bchk;
            unsigned af[4][4], bf[4][2];
#pragma unroll
            for (int mi = 0; mi < 4; mi++) {
                int m = wm * 64 + mi * 16 + arow;
                ldsm_x4(af[mi], a_s + swz(m, ca));
            }
#pragma unroll
            for (int ni = 0; ni < 4; ni++) {
                int n = wn * 32 + ni * 8 + brow;
                ldsm_x2(bf[ni], b_s + swz(n, cb));
            }
#pragma unroll
            for (int mi = 0; mi < 4; mi++)
#pragma unroll
                for (int ni = 0; ni < 4; ni++)
                    mma_f16(acc[mi][ni], af[mi], bf[ni]);
        }
    }
    __syncthreads();
    // ---- epilogue: fp16 plane output ----
#pragma unroll
    for (int mi = 0; mi < 4; mi++) {
#pragma unroll
        for (int ni = 0; ni < 4; ni++) {
            int colc = wn * 32 + ni * 8 + tig * 2;
            int ra = row0 + wm * 64 + mi * 16 + gq;
            int rb = ra + 8;
            if (ra < N_NODES) {
                ushort2 hv;
                hv.x = f16_of(fmaxf(acc[mi][ni][0] + bsm[colc], 0.f));
                hv.y = f16_of(fmaxf(acc[mi][ni][1] + bsm[colc + 1], 0.f));
                *(ushort2*)(Hoh + (size_t)ra * HIDF + colc) = hv;
            }
            if (rb < N_NODES) {
                ushort2 hv;
                hv.x = f16_of(fmaxf(acc[mi][ni][2] + bsm[colc], 0.f));
                hv.y = f16_of(fmaxf(acc[mi][ni][3] + bsm[colc + 1], 0.f));
                *(ushort2*)(Hoh + (size_t)rb * HIDF + colc) = hv;
            }
        }
    }
}

// ---------------- sorted segment-mean pooling (fp16 input, 128 nodes/block) ----------------
__global__ void k_pool(const ushort_t* __restrict__ H) {
    int t = threadIdx.x;
    int base = blockIdx.x * 128;
    if (base >= N_NODES) return;
    int end = min(base + 128, N_NODES);
    int cur = g_batch[base];
    float acc = 0.f;
    int run = 0;
    for (int n = base; n < end; n++) {
        int g = g_batch[n];
        if (g != cur) {
            atomicAdd(&g_pool[cur * HIDF + t], acc);
            if (t == 0) atomicAdd(&g_cnt[cur], run);
            acc = 0.f; run = 0; cur = g;
        }
        acc += f16_to_f32(H[(size_t)n * HIDF + t]);
        run++;
    }
    atomicAdd(&g_pool[cur * HIDF + t], acc);
    if (t == 0) atomicAdd(&g_cnt[cur], run);
}

// ---------------- head: one block per graph, one warp per output ----------------
__global__ void k_head(const float* __restrict__ embed, const float* __restrict__ Wlin,
                       const float* __restrict__ blin, float* __restrict__ out) {
    int g = blockIdx.x;
    int o = threadIdx.x >> 5;
    int lane = threadIdx.x & 31;
    float c = (float)max(g_cnt[g], 1);
    float inv = 1.0f / c;
    const float* wr = Wlin + o * (HIDF + EMBF);
    float s = 0.f;
    for (int k = lane; k < HIDF; k += 32) s += g_pool[g * HIDF + k] * inv * wr[k];
    for (int k = lane; k < EMBF; k += 32) s += embed[g * EMBF + k] * wr[HIDF + k];
#pragma unroll
    for (int off = 16; off > 0; off >>= 1)
        s += __shfl_down_sync(0xFFFFFFFF, s, off);
    if (lane == 0) out[g * OUTF + o] = s + blin[o];
}

// ---------------- launch ----------------
extern "C" void kernel_launch(void* const* d_in, const int* in_sizes, int n_in,
                              void* d_out, int out_size) {
    const float* x     = (const float*)d_in[0];
    const void*  ei    = d_in[1];
    const void*  batch = d_in[2];
    const float* embed = (const float*)d_in[3];
    const float* W1l   = (const float*)d_in[4];
    const float* b1l   = (const float*)d_in[5];
    const float* W1r   = (const float*)d_in[6];
    const float* W2l   = (const float*)d_in[7];
    const float* b2l   = (const float*)d_in[8];
    const float* W2r   = (const float*)d_in[9];
    const float* Wlin  = (const float*)d_in[10];
    const float* blin  = (const float*)d_in[11];
    float* out = (float*)d_out;

    ushort_t *xh_p, *h1h_p, *h2h_p, *ag_p, *wh1_p, *wh2_p;
    cudaGetSymbolAddress((void**)&xh_p,  g_xh);
    cudaGetSymbolAddress((void**)&h1h_p, g_h1h);
    cudaGetSymbolAddress((void**)&h2h_p, g_h2h);
    cudaGetSymbolAddress((void**)&ag_p,  g_ag);
    cudaGetSymbolAddress((void**)&wh1_p, g_wh1);
    cudaGetSymbolAddress((void**)&wh2_p, g_wh2);

    cudaFuncSetAttribute(k_gemm_pipe, cudaFuncAttributeMaxDynamicSharedMemorySize, GSMEM);

    const int TB = 256;
    const int n4 = N_NODES * HIDF / 4;
    k_prep_init<<<(n4 + TB - 1) / TB, TB>>>(x, ei, batch, W1l, W1r, W2l, W2r);   // 1
    k_fill_ell<<<(N_EDGES + TB - 1) / TB, TB>>>(ei);                              // 2

    const int NB = (N_NODES + 127) / 128;
    // layer 1
    k_agg<<<(N_NODES + 7) / 8, 256>>>(xh_p, ag_p);                                // 3
    k_gemm_pipe<<<NB, 256, GSMEM>>>(ag_p, xh_p, wh1_p, b1l, h1h_p);               // 4 <- profiled
    // layer 2
    k_agg<<<(N_NODES + 7) / 8, 256>>>(h1h_p, ag_p);                               // 5
    k_gemm_pipe<<<NB, 256, GSMEM>>>(ag_p, h1h_p, wh2_p, b2l, h2h_p);              // 6
    // pooling + head
    k_pool<<<(N_NODES + 127) / 128, 128>>>(h2h_p);                                 // 7
    k_head<<<N_GRAPHS, 256>>>(embed, Wlin, blin, out);                             // 8
}